// round 4
// baseline (speedup 1.0000x reference)
#include <cuda_runtime.h>
#include <math.h>

// ---------------------------------------------------------------------------
// GCN_45921790329163
// R3: warp-synchronous LSTM, 8 rows/warp, 8x8 register blocking (f32x2),
//     no block barriers in the timestep loop, x-part GEMM overlaps activations.
// ---------------------------------------------------------------------------

#define DEV_INLINE __device__ __forceinline__

constexpr int N_   = 4096;
constexpr int T_   = 512;
constexpr int H_   = 64;
constexpr int G_   = 256;   // 4*H gates
constexpr int F_   = 16;
constexpr int HID_ = 256;
constexpr int NC_  = 10;

// --------------------------- scratch (device globals) ----------------------
__device__ float g_ft[(size_t)N_ * T_ * F_];        // features transposed (n,t,f)
__device__ float g_h0[(size_t)T_ * (N_ / 8) * 512]; // layer0 h, [t][nblk][u][r] blocked
__device__ float g_xs[(size_t)N_ * T_];             // h1[t][n][0] -> (N,T)
__device__ float g_adj[(size_t)N_ * N_];
__device__ float g_mu[N_];
__device__ float g_sd[N_];
__device__ float g_d[N_];
__device__ float g_y[N_ * HID_];
__device__ float g_z[N_ * HID_];

typedef unsigned long long ull;

DEV_INLINE void fma2(ull& acc, ull a, ull b) {
    asm("fma.rn.f32x2 %0, %1, %2, %3;" : "=l"(acc) : "l"(a), "l"(b), "l"(acc));
}
DEV_INLINE ull pack2(float x) {
    ull r; asm("mov.b64 %0, {%1, %1};" : "=l"(r) : "f"(x)); return r;
}
DEV_INLINE ull packab(float lo, float hi) {
    ull r; asm("mov.b64 %0, {%1, %2};" : "=l"(r) : "f"(lo), "f"(hi)); return r;
}
DEV_INLINE float2 unpack2(ull v) {
    float2 f; asm("mov.b64 {%0, %1}, %2;" : "=f"(f.x), "=f"(f.y) : "l"(v)); return f;
}

DEV_INLINE float sigf(float x) { return 1.0f / (1.0f + __expf(-x)); }
DEV_INLINE float tanh_f(float x) {
    float a = fabsf(x);
    float e = __expf(-2.0f * a);
    float t = (1.0f - e) / (1.0f + e);
    return copysignf(t, x);
}

// --------------------------- feature transpose ------------------------------
__global__ __launch_bounds__(256)
void transpose_feat(const float* __restrict__ f, float* __restrict__ ft)
{
    __shared__ float s[16][516];
    int n = blockIdx.x;
    for (int idx = threadIdx.x; idx < F_ * T_; idx += 256) {
        int ff = idx >> 9, t = idx & 511;
        s[ff][t] = f[(size_t)n * (F_ * T_) + idx];
    }
    __syncthreads();
    for (int idx = threadIdx.x; idx < F_ * T_; idx += 256) {
        int t = idx >> 4, ff = idx & 15;
        ft[(size_t)n * (F_ * T_) + idx] = s[ff][t];
    }
}

// --------------------------- LSTM kernel -----------------------------------
// 128 threads = 4 warps; each warp owns 8 batch rows for all T steps.
// Lane owns 8 gate columns (= units 2*lane, 2*lane+1 with gates i,f,g,o) for
// all 8 rows: acc[j][rp] packed f32x2 over row pairs. Inputs staged in
// warp-private smem buffers [k][8rows]; weights shared in smem [KIN][256]
// (column c = 4u+j holds W[gate j, unit u]).
template <int KIN, int LAYER>
__global__ __launch_bounds__(128, 1)
void lstm_kernel(const float* __restrict__ src,     // L0: g_ft ; L1: g_h0
                 float* __restrict__ dst,           // L0: g_h0 ; L1: g_xs
                 const float* __restrict__ w_ih,
                 const float* __restrict__ w_hh,
                 const float* __restrict__ b_ih,
                 const float* __restrict__ b_hh)
{
    constexpr int KI = KIN - H_;     // 16 (L0) or 64 (L1)

    extern __shared__ float smem[];
    float* Wt2  = smem;                              // [KIN][256]
    float* bufs = Wt2 + KIN * G_;                    // per-warp x|h buffers

    const int tid  = threadIdx.x;
    const int lane = tid & 31;
    const int warp = tid >> 5;
    const int n0   = blockIdx.x * 32;
    const int blk  = (n0 >> 3) + warp;               // 8-row block index

    float* xbuf = bufs + warp * (KI * 8 + H_ * 8);
    float* hbuf = xbuf + KI * 8;

    // ---- fill gate-interleaved weights ----
    for (int idx = tid; idx < KIN * G_; idx += 128) {
        int k = idx >> 8, c = idx & 255;
        int uu = c >> 2, j = c & 3;
        int row = j * H_ + uu;
        Wt2[idx] = (k < KI) ? w_ih[row * KI + k] : w_hh[row * H_ + (k - KI)];
    }

    // ---- bias in registers (8 gate cols of this lane) ----
    ull bj[8];
#pragma unroll
    for (int j = 0; j < 8; j++) {
        int u = 2 * lane + (j >> 2), g = j & 3;
        bj[j] = pack2(b_ih[g * H_ + u] + b_hh[g * H_ + u]);
    }

    // ---- zero hbuf, stage x(0) ----
    for (int i = lane; i < H_ * 8; i += 32) hbuf[i] = 0.0f;
    if constexpr (LAYER == 0) {
        int r = lane >> 2, c = lane & 3;
        float4 v = *(const float4*)(src + ((size_t)(n0 + warp * 8 + r) * T_ + 0) * F_ + c * 4);
        xbuf[(4 * c + 0) * 8 + r] = v.x; xbuf[(4 * c + 1) * 8 + r] = v.y;
        xbuf[(4 * c + 2) * 8 + r] = v.z; xbuf[(4 * c + 3) * 8 + r] = v.w;
    } else {
        const float* sb = src + ((size_t)0 * (N_ / 8) + blk) * 512;
#pragma unroll
        for (int j = 0; j < 4; j++)
            *(float4*)(xbuf + j * 128 + lane * 4) = *(const float4*)(sb + j * 128 + lane * 4);
    }
    __syncwarp();
    __syncthreads();   // weights visible to all warps (once)

    ull acc[8][4];

    // ---- initial x-part (t=0) ----
#pragma unroll
    for (int j = 0; j < 8; j++)
#pragma unroll
        for (int rp = 0; rp < 4; rp++) acc[j][rp] = bj[j];

#pragma unroll 4
    for (int k = 0; k < KI; k++) {
        float4 wa = *(const float4*)(Wt2 + (size_t)k * G_ + lane * 8);
        float4 wb = *(const float4*)(Wt2 + (size_t)k * G_ + lane * 8 + 4);
        ulonglong2 va = *(const ulonglong2*)(xbuf + k * 8);
        ulonglong2 vb = *(const ulonglong2*)(xbuf + k * 8 + 4);
        ull w;
        w = pack2(wa.x); fma2(acc[0][0],va.x,w); fma2(acc[0][1],va.y,w); fma2(acc[0][2],vb.x,w); fma2(acc[0][3],vb.y,w);
        w = pack2(wa.y); fma2(acc[1][0],va.x,w); fma2(acc[1][1],va.y,w); fma2(acc[1][2],vb.x,w); fma2(acc[1][3],vb.y,w);
        w = pack2(wa.z); fma2(acc[2][0],va.x,w); fma2(acc[2][1],va.y,w); fma2(acc[2][2],vb.x,w); fma2(acc[2][3],vb.y,w);
        w = pack2(wa.w); fma2(acc[3][0],va.x,w); fma2(acc[3][1],va.y,w); fma2(acc[3][2],vb.x,w); fma2(acc[3][3],vb.y,w);
        w = pack2(wb.x); fma2(acc[4][0],va.x,w); fma2(acc[4][1],va.y,w); fma2(acc[4][2],vb.x,w); fma2(acc[4][3],vb.y,w);
        w = pack2(wb.y); fma2(acc[5][0],va.x,w); fma2(acc[5][1],va.y,w); fma2(acc[5][2],vb.x,w); fma2(acc[5][3],vb.y,w);
        w = pack2(wb.z); fma2(acc[6][0],va.x,w); fma2(acc[6][1],va.y,w); fma2(acc[6][2],vb.x,w); fma2(acc[6][3],vb.y,w);
        w = pack2(wb.w); fma2(acc[7][0],va.x,w); fma2(acc[7][1],va.y,w); fma2(acc[7][2],vb.x,w); fma2(acc[7][3],vb.y,w);
    }

    float c_reg[2][8];
#pragma unroll
    for (int uu = 0; uu < 2; uu++)
#pragma unroll
        for (int p = 0; p < 8; p++) c_reg[uu][p] = 0.0f;

    float4 pf[4];   // prefetch regs

    for (int t = 0; t < T_; t++) {
        // ---- prefetch x(t+1) ----
        if (t + 1 < T_) {
            if constexpr (LAYER == 0) {
                int r = lane >> 2, c = lane & 3;
                pf[0] = *(const float4*)(src + ((size_t)(n0 + warp * 8 + r) * T_ + t + 1) * F_ + c * 4);
            } else {
                const float* sb = src + ((size_t)(t + 1) * (N_ / 8) + blk) * 512;
#pragma unroll
                for (int j = 0; j < 4; j++)
                    pf[j] = *(const float4*)(sb + j * 128 + lane * 4);
            }
        }

        // ---- h-part GEMM: acc += Whh . h(t-1) ----
#pragma unroll 4
        for (int k = 0; k < H_; k++) {
            float4 wa = *(const float4*)(Wt2 + (size_t)(KI + k) * G_ + lane * 8);
            float4 wb = *(const float4*)(Wt2 + (size_t)(KI + k) * G_ + lane * 8 + 4);
            ulonglong2 va = *(const ulonglong2*)(hbuf + k * 8);
            ulonglong2 vb = *(const ulonglong2*)(hbuf + k * 8 + 4);
            ull w;
            w = pack2(wa.x); fma2(acc[0][0],va.x,w); fma2(acc[0][1],va.y,w); fma2(acc[0][2],vb.x,w); fma2(acc[0][3],vb.y,w);
            w = pack2(wa.y); fma2(acc[1][0],va.x,w); fma2(acc[1][1],va.y,w); fma2(acc[1][2],vb.x,w); fma2(acc[1][3],vb.y,w);
            w = pack2(wa.z); fma2(acc[2][0],va.x,w); fma2(acc[2][1],va.y,w); fma2(acc[2][2],vb.x,w); fma2(acc[2][3],vb.y,w);
            w = pack2(wa.w); fma2(acc[3][0],va.x,w); fma2(acc[3][1],va.y,w); fma2(acc[3][2],vb.x,w); fma2(acc[3][3],vb.y,w);
            w = pack2(wb.x); fma2(acc[4][0],va.x,w); fma2(acc[4][1],va.y,w); fma2(acc[4][2],vb.x,w); fma2(acc[4][3],vb.y,w);
            w = pack2(wb.y); fma2(acc[5][0],va.x,w); fma2(acc[5][1],va.y,w); fma2(acc[5][2],vb.x,w); fma2(acc[5][3],vb.y,w);
            w = pack2(wb.z); fma2(acc[6][0],va.x,w); fma2(acc[6][1],va.y,w); fma2(acc[6][2],vb.x,w); fma2(acc[6][3],vb.y,w);
            w = pack2(wb.w); fma2(acc[7][0],va.x,w); fma2(acc[7][1],va.y,w); fma2(acc[7][2],vb.x,w); fma2(acc[7][3],vb.y,w);
        }

        // ---- activations (MUFU) ----
        float h_out[2][8];
#pragma unroll
        for (int uu = 0; uu < 2; uu++) {
#pragma unroll
            for (int rp = 0; rp < 4; rp++) {
                float2 gi = unpack2(acc[4 * uu + 0][rp]);
                float2 gf = unpack2(acc[4 * uu + 1][rp]);
                float2 gg = unpack2(acc[4 * uu + 2][rp]);
                float2 go = unpack2(acc[4 * uu + 3][rp]);
                float c0 = sigf(gf.x) * c_reg[uu][2 * rp]     + sigf(gi.x) * tanh_f(gg.x);
                float c1 = sigf(gf.y) * c_reg[uu][2 * rp + 1] + sigf(gi.y) * tanh_f(gg.y);
                c_reg[uu][2 * rp]     = c0;
                c_reg[uu][2 * rp + 1] = c1;
                h_out[uu][2 * rp]     = sigf(go.x) * tanh_f(c0);
                h_out[uu][2 * rp + 1] = sigf(go.y) * tanh_f(c1);
            }
        }

        // ---- stage x(t+1) into xbuf ----
        if (t + 1 < T_) {
            if constexpr (LAYER == 0) {
                int r = lane >> 2, c = lane & 3;
                xbuf[(4 * c + 0) * 8 + r] = pf[0].x; xbuf[(4 * c + 1) * 8 + r] = pf[0].y;
                xbuf[(4 * c + 2) * 8 + r] = pf[0].z; xbuf[(4 * c + 3) * 8 + r] = pf[0].w;
            } else {
#pragma unroll
                for (int j = 0; j < 4; j++)
                    *(float4*)(xbuf + j * 128 + lane * 4) = pf[j];
            }
        }
        __syncwarp();

        // ---- x-part GEMM for t+1 (overlaps MUFU chain above via ILP) ----
        if (t + 1 < T_) {
#pragma unroll
            for (int j = 0; j < 8; j++)
#pragma unroll
                for (int rp = 0; rp < 4; rp++) acc[j][rp] = bj[j];
#pragma unroll 4
            for (int k = 0; k < KI; k++) {
                float4 wa = *(const float4*)(Wt2 + (size_t)k * G_ + lane * 8);
                float4 wb = *(const float4*)(Wt2 + (size_t)k * G_ + lane * 8 + 4);
                ulonglong2 va = *(const ulonglong2*)(xbuf + k * 8);
                ulonglong2 vb = *(const ulonglong2*)(xbuf + k * 8 + 4);
                ull w;
                w = pack2(wa.x); fma2(acc[0][0],va.x,w); fma2(acc[0][1],va.y,w); fma2(acc[0][2],vb.x,w); fma2(acc[0][3],vb.y,w);
                w = pack2(wa.y); fma2(acc[1][0],va.x,w); fma2(acc[1][1],va.y,w); fma2(acc[1][2],vb.x,w); fma2(acc[1][3],vb.y,w);
                w = pack2(wa.z); fma2(acc[2][0],va.x,w); fma2(acc[2][1],va.y,w); fma2(acc[2][2],vb.x,w); fma2(acc[2][3],vb.y,w);
                w = pack2(wa.w); fma2(acc[3][0],va.x,w); fma2(acc[3][1],va.y,w); fma2(acc[3][2],vb.x,w); fma2(acc[3][3],vb.y,w);
                w = pack2(wb.x); fma2(acc[4][0],va.x,w); fma2(acc[4][1],va.y,w); fma2(acc[4][2],vb.x,w); fma2(acc[4][3],vb.y,w);
                w = pack2(wb.y); fma2(acc[5][0],va.x,w); fma2(acc[5][1],va.y,w); fma2(acc[5][2],vb.x,w); fma2(acc[5][3],vb.y,w);
                w = pack2(wb.z); fma2(acc[6][0],va.x,w); fma2(acc[6][1],va.y,w); fma2(acc[6][2],vb.x,w); fma2(acc[6][3],vb.y,w);
                w = pack2(wb.w); fma2(acc[7][0],va.x,w); fma2(acc[7][1],va.y,w); fma2(acc[7][2],vb.x,w); fma2(acc[7][3],vb.y,w);
            }
        }

        // ---- stage h(t) into hbuf (h-part reads for t are complete) ----
#pragma unroll
        for (int uu = 0; uu < 2; uu++) {
            *(float4*)(hbuf + (2 * lane + uu) * 8)     = make_float4(h_out[uu][0], h_out[uu][1], h_out[uu][2], h_out[uu][3]);
            *(float4*)(hbuf + (2 * lane + uu) * 8 + 4) = make_float4(h_out[uu][4], h_out[uu][5], h_out[uu][6], h_out[uu][7]);
        }

        // ---- global outputs ----
        if constexpr (LAYER == 0) {
            float* db = dst + ((size_t)t * (N_ / 8) + blk) * 512;
#pragma unroll
            for (int uu = 0; uu < 2; uu++) {
                *(float4*)(db + (2 * lane + uu) * 8)     = make_float4(h_out[uu][0], h_out[uu][1], h_out[uu][2], h_out[uu][3]);
                *(float4*)(db + (2 * lane + uu) * 8 + 4) = make_float4(h_out[uu][4], h_out[uu][5], h_out[uu][6], h_out[uu][7]);
            }
        } else {
            if (lane == 0) {
#pragma unroll
                for (int r = 0; r < 8; r++)
                    dst[(size_t)(n0 + warp * 8 + r) * T_ + t] = h_out[0][r];
            }
        }
        __syncwarp();
    }
}

// --------------------------- row stats (mu, std) ----------------------------
__global__ __launch_bounds__(256)
void stats_kernel(const float* __restrict__ xs, float* __restrict__ mu,
                  float* __restrict__ sd)
{
    __shared__ float sh[8], sh2[8];
    int n = blockIdx.x, tid = threadIdx.x;
    float s = 0.f, s2 = 0.f;
    for (int t = tid; t < T_; t += 256) {
        float v = xs[(size_t)n * T_ + t];
        s += v; s2 += v * v;
    }
#pragma unroll
    for (int o = 16; o; o >>= 1) {
        s  += __shfl_xor_sync(0xffffffffu, s, o);
        s2 += __shfl_xor_sync(0xffffffffu, s2, o);
    }
    if ((tid & 31) == 0) { sh[tid >> 5] = s; sh2[tid >> 5] = s2; }
    __syncthreads();
    if (tid == 0) {
        float ts = 0.f, ts2 = 0.f;
        for (int w = 0; w < 8; w++) { ts += sh[w]; ts2 += sh2[w]; }
        float m = ts * (1.0f / T_);
        float var = ts2 * (1.0f / T_) - m * m;
        mu[n] = m;
        sd[n] = sqrtf(fmaxf(var, 0.0f));
    }
}

// --------------------------- corr GEMM (X X^T -> adj), f32x2 ---------------
__global__ __launch_bounds__(256)
void corr_kernel(const float* __restrict__ X, float* __restrict__ adj,
                 const float* __restrict__ mu, const float* __restrict__ sd)
{
    if (blockIdx.x < blockIdx.y) return;
    __shared__ float As[16][68];
    __shared__ float Bs[16][68];
    const int tid = threadIdx.x;
    const int tx = tid & 15, ty = tid >> 4;
    const int row0 = blockIdx.y * 64, col0 = blockIdx.x * 64;
    const int ar = tid >> 2, ac = (tid & 3) << 2;
    ull acc2[2][4];
#pragma unroll
    for (int i = 0; i < 2; i++)
#pragma unroll
        for (int j = 0; j < 4; j++) acc2[i][j] = 0ull;

    for (int k0 = 0; k0 < T_; k0 += 16) {
        float4 a4 = *(const float4*)&X[(size_t)(row0 + ar) * T_ + k0 + ac];
        As[ac + 0][ar] = a4.x; As[ac + 1][ar] = a4.y;
        As[ac + 2][ar] = a4.z; As[ac + 3][ar] = a4.w;
        float4 b4 = *(const float4*)&X[(size_t)(col0 + ar) * T_ + k0 + ac];
        Bs[ac + 0][ar] = b4.x; Bs[ac + 1][ar] = b4.y;
        Bs[ac + 2][ar] = b4.z; Bs[ac + 3][ar] = b4.w;
        __syncthreads();
#pragma unroll
        for (int k = 0; k < 16; k++) {
            float4 av = *(const float4*)&As[k][ty << 2];
            float4 bv = *(const float4*)&Bs[k][tx << 2];
            ull a01 = packab(av.x, av.y), a23 = packab(av.z, av.w);
            ull b0 = pack2(bv.x), b1 = pack2(bv.y), b2 = pack2(bv.z), b3 = pack2(bv.w);
            fma2(acc2[0][0], a01, b0); fma2(acc2[1][0], a23, b0);
            fma2(acc2[0][1], a01, b1); fma2(acc2[1][1], a23, b1);
            fma2(acc2[0][2], a01, b2); fma2(acc2[1][2], a23, b2);
            fma2(acc2[0][3], a01, b3); fma2(acc2[1][3], a23, b3);
        }
        __syncthreads();
    }
    float acc[4][4];
#pragma unroll
    for (int j = 0; j < 4; j++) {
        float2 r01 = unpack2(acc2[0][j]);
        float2 r23 = unpack2(acc2[1][j]);
        acc[0][j] = r01.x; acc[1][j] = r01.y; acc[2][j] = r23.x; acc[3][j] = r23.y;
    }
#pragma unroll
    for (int i = 0; i < 4; i++) {
        int gi = row0 + (ty << 2) + i;
        float mi = mu[gi], si = sd[gi];
#pragma unroll
        for (int j = 0; j < 4; j++) {
            int gj = col0 + (tx << 2) + j;
            float cov = acc[i][j] * (1.0f / T_) - mi * mu[gj];
            float den = si * sd[gj];
            float corr = (den == 0.0f) ? 0.0f : cov / den;
            float a = corr + ((gi == gj) ? 1.0f : 0.0f);
            adj[(size_t)gi * N_ + gj] = a;
            adj[(size_t)gj * N_ + gi] = a;
        }
    }
}

// --------------------------- rowsum -> d = rs^-0.5 --------------------------
__global__ __launch_bounds__(256)
void rowsum_kernel(const float* __restrict__ adj, float* __restrict__ dvec)
{
    __shared__ float sh[8];
    int i = blockIdx.x, tid = threadIdx.x;
    float s = 0.f;
    for (int j = tid; j < N_; j += 256) s += adj[(size_t)i * N_ + j];
#pragma unroll
    for (int o = 16; o; o >>= 1) s += __shfl_xor_sync(0xffffffffu, s, o);
    if ((tid & 31) == 0) sh[tid >> 5] = s;
    __syncthreads();
    if (tid == 0) {
        float ts = 0.f;
        for (int w = 0; w < 8; w++) ts += sh[w];
        dvec[i] = (ts > 0.0f) ? (1.0f / sqrtf(ts)) : 0.0f;
    }
}

// --------------------------- tiled GEMM (NN), f32x2, epilogues --------------
template <int MODE>
__global__ __launch_bounds__(256)
void gemm_nn(const float* __restrict__ A, const float* __restrict__ B,
             float* __restrict__ C, int M, int N, int K,
             const float* __restrict__ dvec, const float* __restrict__ bias)
{
    __shared__ float As[16][68];
    __shared__ float Bs[16][64];
    const int tid = threadIdx.x;
    const int tx = tid & 15, ty = tid >> 4;
    const int row0 = blockIdx.y * 64, col0 = blockIdx.x * 64;
    const int ar = tid >> 2, ac = (tid & 3) << 2;
    const int br = tid >> 4, bc = (tid & 15) << 2;
    ull acc2[2][4];
#pragma unroll
    for (int i = 0; i < 2; i++)
#pragma unroll
        for (int j = 0; j < 4; j++) acc2[i][j] = 0ull;

    for (int k0 = 0; k0 < K; k0 += 16) {
        float4 a4 = *(const float4*)&A[(size_t)(row0 + ar) * K + k0 + ac];
        As[ac + 0][ar] = a4.x; As[ac + 1][ar] = a4.y;
        As[ac + 2][ar] = a4.z; As[ac + 3][ar] = a4.w;
        *(float4*)&Bs[br][bc] = *(const float4*)&B[(size_t)(k0 + br) * N + col0 + bc];
        __syncthreads();
#pragma unroll
        for (int k = 0; k < 16; k++) {
            float4 av = *(const float4*)&As[k][ty << 2];
            float4 bv = *(const float4*)&Bs[k][tx << 2];
            ull a01 = packab(av.x, av.y), a23 = packab(av.z, av.w);
            ull b0 = pack2(bv.x), b1 = pack2(bv.y), b2 = pack2(bv.z), b3 = pack2(bv.w);
            fma2(acc2[0][0], a01, b0); fma2(acc2[1][0], a23, b0);
            fma2(acc2[0][1], a01, b1); fma2(acc2[1][1], a23, b1);
            fma2(acc2[0][2], a01, b2); fma2(acc2[1][2], a23, b2);
            fma2(acc2[0][3], a01, b3); fma2(acc2[1][3], a23, b3);
        }
        __syncthreads();
    }
    float acc[4][4];
#pragma unroll
    for (int j = 0; j < 4; j++) {
        float2 r01 = unpack2(acc2[0][j]);
        float2 r23 = unpack2(acc2[1][j]);
        acc[0][j] = r01.x; acc[1][j] = r01.y; acc[2][j] = r23.x; acc[3][j] = r23.y;
    }
#pragma unroll
    for (int i = 0; i < 4; i++) {
        int gi = row0 + (ty << 2) + i;
        float dv = dvec[gi];
#pragma unroll
        for (int j = 0; j < 4; j++) {
            int gj = col0 + (tx << 2) + j;
            float v = acc[i][j];
            if (MODE == 1) v = dv * v;
            if (MODE == 2) { v = dv * v + bias[gj]; v = fmaxf(v, 0.0f); }
            C[(size_t)gi * N + gj] = v;
        }
    }
}

// --------------------------- classifier -------------------------------------
__global__ void clf_kernel(const float* __restrict__ z, const float* __restrict__ w,
                           const float* __restrict__ b, float* __restrict__ out)
{
    int idx = blockIdx.x * blockDim.x + threadIdx.x;
    if (idx >= N_ * NC_) return;
    int n = idx / NC_, c = idx - n * NC_;
    float s = b[c];
    const float* zr = z + (size_t)n * HID_;
#pragma unroll 8
    for (int h = 0; h < HID_; h++) s += zr[h] * w[h * NC_ + c];
    out[idx] = s;
}

// --------------------------- launch ------------------------------------------
extern "C" void kernel_launch(void* const* d_in, const int* in_sizes, int n_in,
                              void* d_out, int out_size)
{
    const float* features = (const float*)d_in[0];
    const float* w_ih0 = (const float*)d_in[1];
    const float* w_hh0 = (const float*)d_in[2];
    const float* b_ih0 = (const float*)d_in[3];
    const float* b_hh0 = (const float*)d_in[4];
    const float* w_ih1 = (const float*)d_in[5];
    const float* w_hh1 = (const float*)d_in[6];
    const float* b_ih1 = (const float*)d_in[7];
    const float* b_hh1 = (const float*)d_in[8];
    const float* gc1_w = (const float*)d_in[9];
    const float* gc1_b = (const float*)d_in[10];
    const float* gc2_w = (const float*)d_in[11];
    const float* gc2_b = (const float*)d_in[12];
    const float* clf_w = (const float*)d_in[13];
    const float* clf_b = (const float*)d_in[14];
    float* out = (float*)d_out;

    float *p_ft, *p_h0, *p_xs, *p_adj, *p_mu, *p_sd, *p_d, *p_y, *p_z;
    cudaGetSymbolAddress((void**)&p_ft,  g_ft);
    cudaGetSymbolAddress((void**)&p_h0,  g_h0);
    cudaGetSymbolAddress((void**)&p_xs,  g_xs);
    cudaGetSymbolAddress((void**)&p_adj, g_adj);
    cudaGetSymbolAddress((void**)&p_mu,  g_mu);
    cudaGetSymbolAddress((void**)&p_sd,  g_sd);
    cudaGetSymbolAddress((void**)&p_d,   g_d);
    cudaGetSymbolAddress((void**)&p_y,   g_y);
    cudaGetSymbolAddress((void**)&p_z,   g_z);

    const int smem0 = (80  * G_ + 4 * (16 * 8 + 64 * 8)) * 4;  // 92160 B
    const int smem1 = (128 * G_ + 4 * (64 * 8 + 64 * 8)) * 4;  // 147456 B
    cudaFuncSetAttribute((const void*)lstm_kernel<80, 0>,
                         cudaFuncAttributeMaxDynamicSharedMemorySize, smem0);
    cudaFuncSetAttribute((const void*)lstm_kernel<128, 1>,
                         cudaFuncAttributeMaxDynamicSharedMemorySize, smem1);

    // features (N,F,T) -> (N,T,F)
    transpose_feat<<<N_, 256>>>(features, p_ft);

    // LSTM layer 0: g_ft -> g_h0 (blocked layout)
    lstm_kernel<80, 0><<<N_ / 32, 128, smem0>>>(p_ft, p_h0, w_ih0, w_hh0, b_ih0, b_hh0);
    // LSTM layer 1: g_h0 -> g_xs (channel 0)
    lstm_kernel<128, 1><<<N_ / 32, 128, smem1>>>(p_h0, p_xs, w_ih1, w_hh1, b_ih1, b_hh1);

    // adjacency
    stats_kernel<<<N_, 256>>>(p_xs, p_mu, p_sd);
    corr_kernel<<<dim3(N_ / 64, N_ / 64), 256>>>(p_xs, p_adj, p_mu, p_sd);
    rowsum_kernel<<<N_, 256>>>(p_adj, p_d);

    // GCN
    gemm_nn<1><<<dim3(HID_ / 64, N_ / 64), 256>>>(p_xs,  gc1_w, p_y, N_, HID_, T_,   p_d, nullptr);
    gemm_nn<2><<<dim3(HID_ / 64, N_ / 64), 256>>>(p_adj, p_y,   p_z, N_, HID_, N_,   p_d, gc1_b);
    gemm_nn<1><<<dim3(HID_ / 64, N_ / 64), 256>>>(p_z,   gc2_w, p_y, N_, HID_, HID_, p_d, nullptr);
    gemm_nn<2><<<dim3(HID_ / 64, N_ / 64), 256>>>(p_adj, p_y,   p_z, N_, HID_, N_,   p_d, gc2_b);

    // classifier
    clf_kernel<<<(N_ * NC_ + 255) / 256, 256>>>(p_z, clf_w, clf_b, out);
}